// round 4
// baseline (speedup 1.0000x reference)
#include <cuda_runtime.h>
#include <math.h>

#define Bn 64
#define Tn 512
#define En 768
#define Cn 20
#define FULL 0xffffffffu

// scratch (no allocations allowed)
__device__ float g_em[Bn * Tn * Cn];   // emissions [B][T][C]
__device__ float g_norm[Bn];
__device__ float g_score[Bn];

__device__ __forceinline__ float neg_inf() { return __int_as_float(0xff800000); }

// ---------------------------------------------------------------------------
// Kernel 1: emissions = hidden @ fc_w^T + fc_b
// warp per ROW-PAIR (2-row register tile halves smem weight traffic)
// ---------------------------------------------------------------------------
extern "C" __global__ void __launch_bounds__(256, 3)
k_emissions(const float* __restrict__ hidden,
            const float* __restrict__ fc_w,
            const float* __restrict__ fc_b) {
    extern __shared__ float sm[];          // Cn*En weights + Cn bias
    float* wsh = sm;
    float* bsh = sm + Cn * En;
    for (int i = threadIdx.x; i < Cn * En; i += blockDim.x) wsh[i] = fc_w[i];
    if (threadIdx.x < Cn) bsh[threadIdx.x] = fc_b[threadIdx.x];
    __syncthreads();

    const int lane  = threadIdx.x & 31;
    const int warp  = threadIdx.x >> 5;
    const int nwarp = (blockDim.x >> 5) * gridDim.x;
    const float4* w4 = (const float4*)wsh;
    const int npairs = Bn * Tn / 2;

    for (int pair = blockIdx.x * (blockDim.x >> 5) + warp; pair < npairs; pair += nwarp) {
        const float4* h0 = (const float4*)(hidden + (size_t)(2 * pair) * En);
        const float4* h1 = h0 + En / 4;
        float a0[Cn], a1[Cn];
#pragma unroll
        for (int c = 0; c < Cn; c++) { a0[c] = 0.f; a1[c] = 0.f; }

#pragma unroll
        for (int k = 0; k < En / 128; k++) {           // 6 chunks of 128 floats
            float4 x0 = h0[lane + 32 * k];
            float4 x1 = h1[lane + 32 * k];
#pragma unroll
            for (int c = 0; c < Cn; c++) {
                float4 w = w4[c * (En / 4) + lane + 32 * k];
                a0[c] = fmaf(x0.x, w.x, fmaf(x0.y, w.y, fmaf(x0.z, w.z, fmaf(x0.w, w.w, a0[c]))));
                a1[c] = fmaf(x1.x, w.x, fmaf(x1.y, w.y, fmaf(x1.z, w.z, fmaf(x1.w, w.w, a1[c]))));
            }
        }
#pragma unroll
        for (int c = 0; c < Cn; c++) {
#pragma unroll
            for (int o = 16; o; o >>= 1) {
                a0[c] += __shfl_xor_sync(FULL, a0[c], o);
                a1[c] += __shfl_xor_sync(FULL, a1[c], o);
            }
        }
        if (lane == 0) {
            float* out0 = g_em + (size_t)(2 * pair) * Cn;
            float4* o0 = (float4*)out0;
            float4* o1 = (float4*)(out0 + Cn);
            o0[0] = make_float4(a0[0]+bsh[0],   a0[1]+bsh[1],   a0[2]+bsh[2],   a0[3]+bsh[3]);
            o0[1] = make_float4(a0[4]+bsh[4],   a0[5]+bsh[5],   a0[6]+bsh[6],   a0[7]+bsh[7]);
            o0[2] = make_float4(a0[8]+bsh[8],   a0[9]+bsh[9],   a0[10]+bsh[10], a0[11]+bsh[11]);
            o0[3] = make_float4(a0[12]+bsh[12], a0[13]+bsh[13], a0[14]+bsh[14], a0[15]+bsh[15]);
            o0[4] = make_float4(a0[16]+bsh[16], a0[17]+bsh[17], a0[18]+bsh[18], a0[19]+bsh[19]);
            o1[0] = make_float4(a1[0]+bsh[0],   a1[1]+bsh[1],   a1[2]+bsh[2],   a1[3]+bsh[3]);
            o1[1] = make_float4(a1[4]+bsh[4],   a1[5]+bsh[5],   a1[6]+bsh[6],   a1[7]+bsh[7]);
            o1[2] = make_float4(a1[8]+bsh[8],   a1[9]+bsh[9],   a1[10]+bsh[10], a1[11]+bsh[11]);
            o1[3] = make_float4(a1[12]+bsh[12], a1[13]+bsh[13], a1[14]+bsh[14], a1[15]+bsh[15]);
            o1[4] = make_float4(a1[16]+bsh[16], a1[17]+bsh[17], a1[18]+bsh[18], a1[19]+bsh[19]);
        }
    }
}

// ---------------------------------------------------------------------------
// Kernel 2: blocks 0..63  -> numerator score + scaled forward (per batch)
//           blocks 64..127-> viterbi + backtrace, writes path into dout[1..]
// 128 threads stage emissions, warp 0 runs the recurrence
// ---------------------------------------------------------------------------
#define SM_EM    (Tn * Cn * 4)                 // 40960
#define SM_MSK   (Tn * 4)                      // 2048 (reused as path buffer)
#define SM_HIST  ((Tn / 4) * Cn * 4)           // 10240  packed u32 backptrs
#define SM2_SIZE (SM_EM + SM_MSK + SM_HIST + 16)

extern "C" __global__ void __launch_bounds__(128)
k_crf(const int* __restrict__ amask,
      const int* __restrict__ labels,
      const float* __restrict__ start_t,
      const float* __restrict__ end_t,
      const float* __restrict__ trans,
      float* __restrict__ dout) {
    extern __shared__ char smraw[];
    float*    em_sh  = (float*)smraw;
    int*      msk    = (int*)(smraw + SM_EM);
    unsigned* hist32 = (unsigned*)(smraw + SM_EM + SM_MSK);

    const int tid  = threadIdx.x;
    const bool isfwd = (blockIdx.x < Bn);
    const int b = isfwd ? blockIdx.x : blockIdx.x - Bn;

    // stage emissions + mask for this batch (all 4 warps)
    {
        const float4* src = (const float4*)(g_em + (size_t)b * Tn * Cn);
        float4* dst = (float4*)em_sh;
#pragma unroll 4
        for (int i = tid; i < Tn * Cn / 4; i += 128) dst[i] = src[i];
        for (int i = tid; i < Tn; i += 128) msk[i] = amask[b * Tn + i];
    }
    __syncthreads();
    if (tid >= 32) return;                 // warps 1..3 retire

    const int lane = tid;
    const bool act = lane < Cn;
    const int jj = act ? lane : 0;          // clamped state index (avoid OOB)

    if (isfwd) {
        // ---- numerator: gold path score ----
        float ns = 0.f; int msum = 0;
        for (int t = lane; t < Tn; t += 32) {
            int tg = labels[b * Tn + t];
            msum += msk[t];
            if (t == 0) {
                ns += start_t[tg] + em_sh[tg];
            } else if (msk[t]) {
                int tp = labels[b * Tn + t - 1];
                ns += trans[tp * Cn + tg] + em_sh[t * Cn + tg];
            }
        }
        for (int o = 16; o; o >>= 1) {
            ns   += __shfl_xor_sync(FULL, ns, o);
            msum += __shfl_xor_sync(FULL, msum, o);
        }
        if (lane == 0) {
            int se = msum - 1;
            g_score[b] = ns + end_t[labels[b * Tn + se]];
        }

        // ---- denominator: scaled linear-domain forward ----
        float Mc[Cn];
#pragma unroll
        for (int i = 0; i < Cn; i++) Mc[i] = act ? expf(trans[i * Cn + jj]) : 0.f;

        float p = act ? expf(start_t[jj] + em_sh[jj]) : 0.f;
        float logZ = 0.f;

        // prefetched operands for step t
        float emc = em_sh[Cn + jj];
        int   mkc = msk[1];

#pragma unroll 2
        for (int t = 1; t < Tn; t++) {
            // prefetch next step (reads 1 past end land in adjacent smem regions: safe)
            float emn = em_sh[(t + 1) * Cn + jj];
            int   mkn = msk[t + 1];
            float Ev = __expf(emc);                  // off critical path
            float q0 = 0.f, q1 = 0.f, q2 = 0.f, q3 = 0.f;
#pragma unroll
            for (int i = 0; i < Cn; i += 4) {
                q0 = fmaf(__shfl_sync(FULL, p, i + 0), Mc[i + 0], q0);
                q1 = fmaf(__shfl_sync(FULL, p, i + 1), Mc[i + 1], q1);
                q2 = fmaf(__shfl_sync(FULL, p, i + 2), Mc[i + 2], q2);
                q3 = fmaf(__shfl_sync(FULL, p, i + 3), Mc[i + 3], q3);
            }
            float r = ((q0 + q1) + (q2 + q3)) * Ev;
            p = (mkc > 0) ? r : p;                   // lanes>=20 stay 0
            if ((t & 15) == 0) {                     // renormalize every 16 steps
                float s = p;
                for (int o = 16; o; o >>= 1) s += __shfl_xor_sync(FULL, s, o);
                p *= __fdividef(1.f, s);
                logZ += __logf(s);
            }
            emc = emn; mkc = mkn;
        }
        float fin = act ? p * __expf(end_t[jj]) : 0.f;
        for (int o = 16; o; o >>= 1) fin += __shfl_xor_sync(FULL, fin, o);
        if (lane == 0) g_norm[b] = logZ + __logf(fin);

    } else {
        // ---- viterbi: FMNMX max-tree on critical path, argmax off-path ----
        float Tc[Cn];
#pragma unroll
        for (int i = 0; i < Cn; i++) Tc[i] = act ? trans[i * Cn + jj] : 0.f;

        float a = act ? (start_t[jj] + em_sh[jj]) : neg_inf();

        float emc = em_sh[Cn + jj];
        int   mkc = msk[1];
        unsigned bp = 0;                    // packed backpointers (4 per u32)

#pragma unroll 2
        for (int t = 1; t < Tn; t++) {
            float emn = em_sh[(t + 1) * Cn + jj];
            int   mkn = msk[t + 1];

            float v[Cn];
#pragma unroll
            for (int i = 0; i < Cn; i++) v[i] = __shfl_sync(FULL, a, i) + Tc[i];

            // value max: pure FMNMX tree (lat 4, depth 5)
            float m0 = fmaxf(v[0],  v[1]);
            float m1 = fmaxf(v[2],  v[3]);
            float m2 = fmaxf(v[4],  v[5]);
            float m3 = fmaxf(v[6],  v[7]);
            float m4 = fmaxf(v[8],  v[9]);
            float m5 = fmaxf(v[10], v[11]);
            float m6 = fmaxf(v[12], v[13]);
            float m7 = fmaxf(v[14], v[15]);
            float m8 = fmaxf(v[16], v[17]);
            float m9 = fmaxf(v[18], v[19]);
            float n0 = fmaxf(m0, m1);
            float n1 = fmaxf(m2, m3);
            float n2 = fmaxf(m4, m5);
            float n3 = fmaxf(m6, m7);
            float n4 = fmaxf(m8, m9);
            float best = fmaxf(fmaxf(fmaxf(n0, n1), fmaxf(n2, n3)), n4);

            // recurrence continues immediately
            float na = best + emc;
            a = (mkc > 0) ? na : a;         // garbage on inactive lanes, never read

            // argmax (first max wins): exact equality mask, lowest set bit.
            unsigned eqm = 0;
#pragma unroll
            for (int i = 0; i < Cn; i++) eqm |= (v[i] == best) ? (1u << i) : 0u;
            int bi = __ffs(eqm) - 1;

            int idx = t - 1;
            bp |= (unsigned)bi << ((idx & 3) * 8);
            if ((idx & 3) == 3) {
                if (act) hist32[(idx >> 2) * Cn + lane] = bp;   // conflict-free 4B STS
                bp = 0;
            }
            emc = emn; mkc = mkn;
        }
        if (act) hist32[((Tn - 2) >> 2) * Cn + lane] = bp;      // flush partial (idx 508..510)

        // final argmax over states (first max on ties)
        float fv = act ? a + end_t[jj] : neg_inf();
        int fi = lane;
        for (int o = 16; o; o >>= 1) {
            float ov = __shfl_xor_sync(FULL, fv, o);
            int   oi = __shfl_xor_sync(FULL, fi, o);
            bool tk = (ov > fv) || (ov == fv && oi < fi);
            fv = tk ? ov : fv;
            fi = tk ? oi : fi;
        }
        __syncwarp();
        float* pathf = (float*)msk;         // reuse mask buffer (mask no longer needed)
        if (lane == 0) {
            int tg = fi;
            pathf[Tn - 1] = (float)(tg + 1);
            for (int t = Tn - 2; t >= 0; t--) {
                unsigned w = hist32[(t >> 2) * Cn + tg];
                tg = (int)((w >> ((t & 3) * 8)) & 0xffu);
                pathf[t] = (float)(tg + 1);
            }
        }
        __syncwarp();
        // coalesced path write-out
        float* od = dout + 1 + b * Tn;
#pragma unroll
        for (int i = 0; i < Tn / 32; i++) od[lane + 32 * i] = pathf[lane + 32 * i];
    }
}

// ---------------------------------------------------------------------------
// Kernel 3: loss = mean(norm - score)   (one warp)
// ---------------------------------------------------------------------------
extern "C" __global__ void k_loss(float* __restrict__ dout) {
    int i = threadIdx.x;                          // 32 threads
    float v = g_norm[i] - g_score[i];
    v += g_norm[i + 32] - g_score[i + 32];
    for (int o = 16; o; o >>= 1) v += __shfl_xor_sync(FULL, v, o);
    if (i == 0) dout[0] = v / (float)Bn;
}

// ---------------------------------------------------------------------------
extern "C" void kernel_launch(void* const* d_in, const int* in_sizes, int n_in,
                              void* d_out, int out_size) {
    const float* hidden = (const float*)d_in[0];
    const int*   amask  = (const int*)d_in[1];
    const int*   labels = (const int*)d_in[2];
    const float* fc_w   = (const float*)d_in[3];
    const float* fc_b   = (const float*)d_in[4];
    const float* st     = (const float*)d_in[5];
    const float* en     = (const float*)d_in[6];
    const float* tr     = (const float*)d_in[7];
    float* dout = (float*)d_out;

    const int smem1 = (Cn * En + Cn) * 4;
    (void)cudaFuncSetAttribute((const void*)k_emissions,
                               cudaFuncAttributeMaxDynamicSharedMemorySize, smem1);
    (void)cudaFuncSetAttribute((const void*)k_crf,
                               cudaFuncAttributeMaxDynamicSharedMemorySize, SM2_SIZE);

    k_emissions<<<444, 256, smem1>>>(hidden, fc_w, fc_b);   // 3 blocks/SM
    k_crf<<<2 * Bn, 128, SM2_SIZE>>>(amask, labels, st, en, tr, dout);
    k_loss<<<1, 32>>>(dout);
}

// round 5
// speedup vs baseline: 1.3582x; 1.3582x over previous
#include <cuda_runtime.h>
#include <math.h>

#define Bn 64
#define Tn 512
#define En 768
#define Cn 20
#define FULL 0xffffffffu

// scratch (no allocations allowed)
__device__ float g_em[Bn * Tn * Cn];   // emissions [B][T][C]
__device__ float g_norm[Bn];
__device__ float g_score[Bn];

__device__ __forceinline__ float neg_inf() { return __int_as_float(0xff800000); }

// ---------------------------------------------------------------------------
// Kernel 1: emissions = hidden @ fc_w^T + fc_b
// warp per ROW-PAIR (2-row register tile halves smem weight traffic)
// launch_bounds(256,2): reg cap 128 (no spills; needs ~95), 2 blocks/SM
// ---------------------------------------------------------------------------
extern "C" __global__ void __launch_bounds__(256, 2)
k_emissions(const float* __restrict__ hidden,
            const float* __restrict__ fc_w,
            const float* __restrict__ fc_b) {
    extern __shared__ float sm[];          // Cn*En weights + Cn bias
    float* wsh = sm;
    float* bsh = sm + Cn * En;
    for (int i = threadIdx.x; i < Cn * En; i += blockDim.x) wsh[i] = fc_w[i];
    if (threadIdx.x < Cn) bsh[threadIdx.x] = fc_b[threadIdx.x];
    __syncthreads();

    const int lane  = threadIdx.x & 31;
    const int warp  = threadIdx.x >> 5;
    const int nwarp = (blockDim.x >> 5) * gridDim.x;
    const float4* w4 = (const float4*)wsh;
    const int npairs = Bn * Tn / 2;

    for (int pair = blockIdx.x * (blockDim.x >> 5) + warp; pair < npairs; pair += nwarp) {
        const float4* h0 = (const float4*)(hidden + (size_t)(2 * pair) * En);
        const float4* h1 = h0 + En / 4;
        float a0[Cn], a1[Cn];
#pragma unroll
        for (int c = 0; c < Cn; c++) { a0[c] = 0.f; a1[c] = 0.f; }

#pragma unroll
        for (int k = 0; k < En / 128; k++) {           // 6 chunks of 128 floats
            float4 x0 = h0[lane + 32 * k];
            float4 x1 = h1[lane + 32 * k];
#pragma unroll
            for (int c = 0; c < Cn; c++) {
                float4 w = w4[c * (En / 4) + lane + 32 * k];
                a0[c] = fmaf(x0.x, w.x, fmaf(x0.y, w.y, fmaf(x0.z, w.z, fmaf(x0.w, w.w, a0[c]))));
                a1[c] = fmaf(x1.x, w.x, fmaf(x1.y, w.y, fmaf(x1.z, w.z, fmaf(x1.w, w.w, a1[c]))));
            }
        }
#pragma unroll
        for (int c = 0; c < Cn; c++) {
#pragma unroll
            for (int o = 16; o; o >>= 1) {
                a0[c] += __shfl_xor_sync(FULL, a0[c], o);
                a1[c] += __shfl_xor_sync(FULL, a1[c], o);
            }
        }
        if (lane == 0) {
            float* out0 = g_em + (size_t)(2 * pair) * Cn;
            float4* o0 = (float4*)out0;
            float4* o1 = (float4*)(out0 + Cn);
            o0[0] = make_float4(a0[0]+bsh[0],   a0[1]+bsh[1],   a0[2]+bsh[2],   a0[3]+bsh[3]);
            o0[1] = make_float4(a0[4]+bsh[4],   a0[5]+bsh[5],   a0[6]+bsh[6],   a0[7]+bsh[7]);
            o0[2] = make_float4(a0[8]+bsh[8],   a0[9]+bsh[9],   a0[10]+bsh[10], a0[11]+bsh[11]);
            o0[3] = make_float4(a0[12]+bsh[12], a0[13]+bsh[13], a0[14]+bsh[14], a0[15]+bsh[15]);
            o0[4] = make_float4(a0[16]+bsh[16], a0[17]+bsh[17], a0[18]+bsh[18], a0[19]+bsh[19]);
            o1[0] = make_float4(a1[0]+bsh[0],   a1[1]+bsh[1],   a1[2]+bsh[2],   a1[3]+bsh[3]);
            o1[1] = make_float4(a1[4]+bsh[4],   a1[5]+bsh[5],   a1[6]+bsh[6],   a1[7]+bsh[7]);
            o1[2] = make_float4(a1[8]+bsh[8],   a1[9]+bsh[9],   a1[10]+bsh[10], a1[11]+bsh[11]);
            o1[3] = make_float4(a1[12]+bsh[12], a1[13]+bsh[13], a1[14]+bsh[14], a1[15]+bsh[15]);
            o1[4] = make_float4(a1[16]+bsh[16], a1[17]+bsh[17], a1[18]+bsh[18], a1[19]+bsh[19]);
        }
    }
}

// ---------------------------------------------------------------------------
// Kernel 2: blocks 0..63  -> numerator + scaled forward (warp 0)
//           blocks 64..127-> two-pass viterbi (pass1 warp0, pass2 all threads)
// ---------------------------------------------------------------------------
#define SM_EM    (Tn * Cn * 4)                 // 40960  emissions -> a trajectory
#define SM_MSK   (Tn * 4)                      // 2048   mask -> path buffer
#define SM_HIST  (Tn * Cn)                     // 10240  u8 backpointers
#define SM2_SIZE (SM_EM + SM_MSK + SM_HIST + 16)

extern "C" __global__ void __launch_bounds__(128)
k_crf(const int* __restrict__ amask,
      const int* __restrict__ labels,
      const float* __restrict__ start_t,
      const float* __restrict__ end_t,
      const float* __restrict__ trans,
      float* __restrict__ dout) {
    extern __shared__ char smraw[];
    float*         em_sh = (float*)smraw;
    int*           msk   = (int*)(smraw + SM_EM);
    unsigned char* hist8 = (unsigned char*)(smraw + SM_EM + SM_MSK);
    int*           misc  = (int*)(smraw + SM_EM + SM_MSK + SM_HIST);

    const int tid  = threadIdx.x;
    const bool isfwd = (blockIdx.x < Bn);
    const int b = isfwd ? blockIdx.x : blockIdx.x - Bn;

    // stage emissions + mask for this batch (all 4 warps)
    {
        const float4* src = (const float4*)(g_em + (size_t)b * Tn * Cn);
        float4* dst = (float4*)em_sh;
#pragma unroll 4
        for (int i = tid; i < Tn * Cn / 4; i += 128) dst[i] = src[i];
        for (int i = tid; i < Tn; i += 128) msk[i] = amask[b * Tn + i];
    }
    __syncthreads();

    const int lane = tid & 31;
    const bool act = lane < Cn;
    const int jj = act ? lane : 0;

    if (isfwd) {
        if (tid >= 32) return;
        // ---- numerator: gold path score ----
        float ns = 0.f; int msum = 0;
        for (int t = lane; t < Tn; t += 32) {
            int tg = labels[b * Tn + t];
            msum += msk[t];
            if (t == 0) {
                ns += start_t[tg] + em_sh[tg];
            } else if (msk[t]) {
                int tp = labels[b * Tn + t - 1];
                ns += trans[tp * Cn + tg] + em_sh[t * Cn + tg];
            }
        }
        for (int o = 16; o; o >>= 1) {
            ns   += __shfl_xor_sync(FULL, ns, o);
            msum += __shfl_xor_sync(FULL, msum, o);
        }
        if (lane == 0) {
            int se = msum - 1;
            g_score[b] = ns + end_t[labels[b * Tn + se]];
        }

        // ---- denominator: scaled linear-domain forward ----
        float Mc[Cn];
#pragma unroll
        for (int i = 0; i < Cn; i++) Mc[i] = act ? expf(trans[i * Cn + jj]) : 0.f;

        float p = act ? expf(start_t[jj] + em_sh[jj]) : 0.f;
        float logZ = 0.f;
        float emc = em_sh[Cn + jj];
        int   mkc = msk[1];

        for (int t = 1; t < Tn; t++) {
            float emn = em_sh[(t + 1) * Cn + jj];   // overrun lands in msk: harmless
            int   mkn = msk[t + 1];
            float Ev = __expf(emc);
            float q0 = 0.f, q1 = 0.f, q2 = 0.f, q3 = 0.f;
#pragma unroll
            for (int i = 0; i < Cn; i += 4) {
                q0 = fmaf(__shfl_sync(FULL, p, i + 0), Mc[i + 0], q0);
                q1 = fmaf(__shfl_sync(FULL, p, i + 1), Mc[i + 1], q1);
                q2 = fmaf(__shfl_sync(FULL, p, i + 2), Mc[i + 2], q2);
                q3 = fmaf(__shfl_sync(FULL, p, i + 3), Mc[i + 3], q3);
            }
            float r = ((q0 + q1) + (q2 + q3)) * Ev;
            p = (mkc > 0) ? r : p;
            if ((t & 15) == 0) {
                float s = p;
                for (int o = 16; o; o >>= 1) s += __shfl_xor_sync(FULL, s, o);
                p *= __fdividef(1.f, s);
                logZ += __logf(s);
            }
            emc = emn; mkc = mkn;
        }
        float fin = act ? p * __expf(end_t[jj]) : 0.f;
        for (int o = 16; o; o >>= 1) fin += __shfl_xor_sync(FULL, fin, o);
        if (lane == 0) g_norm[b] = logZ + __logf(fin);
        return;
    }

    // ======================= viterbi block =======================
    if (tid < 32) {
        // ---- pass 1: value recurrence only (warp 0); store a_t over em_sh[t]
        float Tc[Cn];
#pragma unroll
        for (int i = 0; i < Cn; i++) Tc[i] = act ? trans[i * Cn + jj] : 0.f;

        float a = act ? (start_t[jj] + em_sh[jj]) : neg_inf();
        if (act) em_sh[jj] = a;                      // a_0 over slot 0

        float emc = em_sh[Cn + jj];
        int   mkc = msk[1];

        for (int t = 1; t < Tn; t++) {
            float emn = em_sh[(t + 1) * Cn + jj];    // slot t+1 untouched yet
            int   mkn = msk[t + 1];

            float v[Cn];
#pragma unroll
            for (int i = 0; i < Cn; i++) v[i] = __shfl_sync(FULL, a, i) + Tc[i];

            float m0 = fmaxf(v[0],  v[1]);
            float m1 = fmaxf(v[2],  v[3]);
            float m2 = fmaxf(v[4],  v[5]);
            float m3 = fmaxf(v[6],  v[7]);
            float m4 = fmaxf(v[8],  v[9]);
            float m5 = fmaxf(v[10], v[11]);
            float m6 = fmaxf(v[12], v[13]);
            float m7 = fmaxf(v[14], v[15]);
            float m8 = fmaxf(v[16], v[17]);
            float m9 = fmaxf(v[18], v[19]);
            float n0 = fmaxf(m0, m1);
            float n1 = fmaxf(m2, m3);
            float n2 = fmaxf(m4, m5);
            float n3 = fmaxf(m6, m7);
            float n4 = fmaxf(m8, m9);
            float best = fmaxf(fmaxf(fmaxf(n0, n1), fmaxf(n2, n3)), n4);

            float na = best + emc;
            a = (mkc > 0) ? na : a;
            if (act) em_sh[t * Cn + jj] = a;         // post-mask a_t
            emc = emn; mkc = mkn;
        }

        // final argmax over states (first max on ties)
        float fv = act ? a + end_t[jj] : neg_inf();
        int fi = lane;
        for (int o = 16; o; o >>= 1) {
            float ov = __shfl_xor_sync(FULL, fv, o);
            int   oi = __shfl_xor_sync(FULL, fi, o);
            bool tk = (ov > fv) || (ov == fv && oi < fi);
            fv = tk ? ov : fv;
            fi = tk ? oi : fi;
        }
        if (lane == 0) misc[0] = fi;
    }
    __syncthreads();

    // ---- pass 2: backpointers in parallel from stored a trajectory ----
    if (tid < 120) {
        const int j = tid % Cn;          // my target state
        const int g = tid / Cn;          // 0..5
        float Tj[Cn];
#pragma unroll
        for (int i = 0; i < Cn; i++) Tj[i] = trans[i * Cn + j];

        for (int t = 1 + g; t < Tn; t += 6) {
            const float4* ap = (const float4*)(em_sh + (t - 1) * Cn);
            float4 A0 = ap[0], A1 = ap[1], A2 = ap[2], A3 = ap[3], A4 = ap[4];
            float v[Cn];
            v[0] = A0.x + Tj[0];  v[1] = A0.y + Tj[1];  v[2] = A0.z + Tj[2];  v[3] = A0.w + Tj[3];
            v[4] = A1.x + Tj[4];  v[5] = A1.y + Tj[5];  v[6] = A1.z + Tj[6];  v[7] = A1.w + Tj[7];
            v[8] = A2.x + Tj[8];  v[9] = A2.y + Tj[9];  v[10] = A2.z + Tj[10]; v[11] = A2.w + Tj[11];
            v[12] = A3.x + Tj[12]; v[13] = A3.y + Tj[13]; v[14] = A3.z + Tj[14]; v[15] = A3.w + Tj[15];
            v[16] = A4.x + Tj[16]; v[17] = A4.y + Tj[17]; v[18] = A4.z + Tj[18]; v[19] = A4.w + Tj[19];

            float m0 = fmaxf(v[0],  v[1]);
            float m1 = fmaxf(v[2],  v[3]);
            float m2 = fmaxf(v[4],  v[5]);
            float m3 = fmaxf(v[6],  v[7]);
            float m4 = fmaxf(v[8],  v[9]);
            float m5 = fmaxf(v[10], v[11]);
            float m6 = fmaxf(v[12], v[13]);
            float m7 = fmaxf(v[14], v[15]);
            float m8 = fmaxf(v[16], v[17]);
            float m9 = fmaxf(v[18], v[19]);
            float best = fmaxf(fmaxf(fmaxf(fmaxf(m0, m1), fmaxf(m2, m3)),
                                     fmaxf(fmaxf(m4, m5), fmaxf(m6, m7))),
                               fmaxf(m8, m9));
            unsigned eqm = 0;
#pragma unroll
            for (int i = 0; i < Cn; i++) eqm |= (v[i] == best) ? (1u << i) : 0u;
            hist8[(t - 1) * Cn + j] = (unsigned char)(__ffs(eqm) - 1);
        }
    }
    __syncthreads();

    // ---- serial backtrace into smem, then coalesced write-out ----
    float* pathf = (float*)msk;            // mask no longer needed
    if (tid == 0) {
        int tg = misc[0];
        pathf[Tn - 1] = (float)(tg + 1);
        for (int t = Tn - 2; t >= 0; t--) {
            tg = hist8[t * Cn + tg];
            pathf[t] = (float)(tg + 1);
        }
    }
    __syncthreads();
    float* od = dout + 1 + b * Tn;
#pragma unroll
    for (int i = 0; i < Tn / 128; i++) od[tid + 128 * i] = pathf[tid + 128 * i];
}

// ---------------------------------------------------------------------------
// Kernel 3: loss = mean(norm - score)   (one warp)
// ---------------------------------------------------------------------------
extern "C" __global__ void k_loss(float* __restrict__ dout) {
    int i = threadIdx.x;                          // 32 threads
    float v = g_norm[i] - g_score[i];
    v += g_norm[i + 32] - g_score[i + 32];
    for (int o = 16; o; o >>= 1) v += __shfl_xor_sync(FULL, v, o);
    if (i == 0) dout[0] = v / (float)Bn;
}

// ---------------------------------------------------------------------------
extern "C" void kernel_launch(void* const* d_in, const int* in_sizes, int n_in,
                              void* d_out, int out_size) {
    const float* hidden = (const float*)d_in[0];
    const int*   amask  = (const int*)d_in[1];
    const int*   labels = (const int*)d_in[2];
    const float* fc_w   = (const float*)d_in[3];
    const float* fc_b   = (const float*)d_in[4];
    const float* st     = (const float*)d_in[5];
    const float* en     = (const float*)d_in[6];
    const float* tr     = (const float*)d_in[7];
    float* dout = (float*)d_out;

    const int smem1 = (Cn * En + Cn) * 4;
    (void)cudaFuncSetAttribute((const void*)k_emissions,
                               cudaFuncAttributeMaxDynamicSharedMemorySize, smem1);
    (void)cudaFuncSetAttribute((const void*)k_crf,
                               cudaFuncAttributeMaxDynamicSharedMemorySize, SM2_SIZE);

    k_emissions<<<296, 256, smem1>>>(hidden, fc_w, fc_b);   // 2 blocks/SM
    k_crf<<<2 * Bn, 128, SM2_SIZE>>>(amask, labels, st, en, tr, dout);
    k_loss<<<1, 32>>>(dout);
}

// round 6
// speedup vs baseline: 4.1022x; 3.0203x over previous
#include <cuda_runtime.h>
#include <math.h>

#define Bn 64
#define Tn 512
#define En 768
#define Cn 20
#define FULL 0xffffffffu

// scratch (no allocations allowed)
__device__ float g_em[Bn * Tn * Cn];   // emissions [B][T][C]
__device__ float g_norm[Bn];
__device__ float g_score[Bn];

__device__ __forceinline__ float neg_inf() { return __int_as_float(0xff800000); }

// ---------------------------------------------------------------------------
// Kernel 1: emissions = hidden @ fc_w^T + fc_b
// warp per ROW-PAIR (2-row register tile halves smem weight traffic)
// k-loop NOT unrolled: keeps live set ~64 regs -> no spills
// ---------------------------------------------------------------------------
extern "C" __global__ void __launch_bounds__(256)
k_emissions(const float* __restrict__ hidden,
            const float* __restrict__ fc_w,
            const float* __restrict__ fc_b) {
    extern __shared__ float sm[];          // Cn*En weights + Cn bias
    float* wsh = sm;
    float* bsh = sm + Cn * En;
    for (int i = threadIdx.x; i < Cn * En; i += blockDim.x) wsh[i] = fc_w[i];
    if (threadIdx.x < Cn) bsh[threadIdx.x] = fc_b[threadIdx.x];
    __syncthreads();

    const int lane  = threadIdx.x & 31;
    const int warp  = threadIdx.x >> 5;
    const int nwarp = (blockDim.x >> 5) * gridDim.x;
    const float4* w4 = (const float4*)wsh;
    const int npairs = Bn * Tn / 2;

    for (int pair = blockIdx.x * (blockDim.x >> 5) + warp; pair < npairs; pair += nwarp) {
        const float4* h0 = (const float4*)(hidden + (size_t)(2 * pair) * En);
        const float4* h1 = h0 + En / 4;
        float a0[Cn], a1[Cn];
#pragma unroll
        for (int c = 0; c < Cn; c++) { a0[c] = 0.f; a1[c] = 0.f; }

#pragma unroll 1
        for (int k = 0; k < En / 128; k++) {           // 6 chunks, NOT unrolled
            float4 x0 = h0[lane + 32 * k];
            float4 x1 = h1[lane + 32 * k];
#pragma unroll
            for (int c = 0; c < Cn; c++) {
                float4 w = w4[c * (En / 4) + lane + 32 * k];
                a0[c] = fmaf(x0.x, w.x, fmaf(x0.y, w.y, fmaf(x0.z, w.z, fmaf(x0.w, w.w, a0[c]))));
                a1[c] = fmaf(x1.x, w.x, fmaf(x1.y, w.y, fmaf(x1.z, w.z, fmaf(x1.w, w.w, a1[c]))));
            }
        }
#pragma unroll
        for (int c = 0; c < Cn; c++) {
#pragma unroll
            for (int o = 16; o; o >>= 1) {
                a0[c] += __shfl_xor_sync(FULL, a0[c], o);
                a1[c] += __shfl_xor_sync(FULL, a1[c], o);
            }
        }
        if (lane == 0) {
            float* out0 = g_em + (size_t)(2 * pair) * Cn;
            float4* o0 = (float4*)out0;
            float4* o1 = (float4*)(out0 + Cn);
            o0[0] = make_float4(a0[0]+bsh[0],   a0[1]+bsh[1],   a0[2]+bsh[2],   a0[3]+bsh[3]);
            o0[1] = make_float4(a0[4]+bsh[4],   a0[5]+bsh[5],   a0[6]+bsh[6],   a0[7]+bsh[7]);
            o0[2] = make_float4(a0[8]+bsh[8],   a0[9]+bsh[9],   a0[10]+bsh[10], a0[11]+bsh[11]);
            o0[3] = make_float4(a0[12]+bsh[12], a0[13]+bsh[13], a0[14]+bsh[14], a0[15]+bsh[15]);
            o0[4] = make_float4(a0[16]+bsh[16], a0[17]+bsh[17], a0[18]+bsh[18], a0[19]+bsh[19]);
            o1[0] = make_float4(a1[0]+bsh[0],   a1[1]+bsh[1],   a1[2]+bsh[2],   a1[3]+bsh[3]);
            o1[1] = make_float4(a1[4]+bsh[4],   a1[5]+bsh[5],   a1[6]+bsh[6],   a1[7]+bsh[7]);
            o1[2] = make_float4(a1[8]+bsh[8],   a1[9]+bsh[9],   a1[10]+bsh[10], a1[11]+bsh[11]);
            o1[3] = make_float4(a1[12]+bsh[12], a1[13]+bsh[13], a1[14]+bsh[14], a1[15]+bsh[15]);
            o1[4] = make_float4(a1[16]+bsh[16], a1[17]+bsh[17], a1[18]+bsh[18], a1[19]+bsh[19]);
        }
    }
}

// ---------------------------------------------------------------------------
// Kernel 2: blocks 0..63  -> numerator + scaled forward (warp 0)
//           blocks 64..127-> two-pass viterbi (pass1 warp0, pass2 all threads)
// ---------------------------------------------------------------------------
#define SM_EM    (Tn * Cn * 4)                 // 40960  emissions -> a trajectory
#define SM_MSK   (Tn * 4)                      // 2048   mask -> path buffer
#define SM_HIST  (Tn * Cn)                     // 10240  u8 backpointers
#define SM2_SIZE (SM_EM + SM_MSK + SM_HIST + 16)

extern "C" __global__ void __launch_bounds__(128)
k_crf(const int* __restrict__ amask,
      const int* __restrict__ labels,
      const float* __restrict__ start_t,
      const float* __restrict__ end_t,
      const float* __restrict__ trans,
      float* __restrict__ dout) {
    extern __shared__ char smraw[];
    float*         em_sh = (float*)smraw;
    int*           msk   = (int*)(smraw + SM_EM);
    unsigned char* hist8 = (unsigned char*)(smraw + SM_EM + SM_MSK);
    int*           misc  = (int*)(smraw + SM_EM + SM_MSK + SM_HIST);

    const int tid  = threadIdx.x;
    const bool isfwd = (blockIdx.x < Bn);
    const int b = isfwd ? blockIdx.x : blockIdx.x - Bn;

    // stage emissions + mask for this batch (all 4 warps)
    {
        const float4* src = (const float4*)(g_em + (size_t)b * Tn * Cn);
        float4* dst = (float4*)em_sh;
#pragma unroll 4
        for (int i = tid; i < Tn * Cn / 4; i += 128) dst[i] = src[i];
        for (int i = tid; i < Tn; i += 128) msk[i] = amask[b * Tn + i];
    }
    __syncthreads();

    const int lane = tid & 31;
    const bool act = lane < Cn;
    const int jj = act ? lane : 0;

    if (isfwd) {
        if (tid >= 32) return;
        // ---- numerator: gold path score ----
        float ns = 0.f; int msum = 0;
        for (int t = lane; t < Tn; t += 32) {
            int tg = labels[b * Tn + t];
            msum += msk[t];
            if (t == 0) {
                ns += start_t[tg] + em_sh[tg];
            } else if (msk[t]) {
                int tp = labels[b * Tn + t - 1];
                ns += trans[tp * Cn + tg] + em_sh[t * Cn + tg];
            }
        }
        for (int o = 16; o; o >>= 1) {
            ns   += __shfl_xor_sync(FULL, ns, o);
            msum += __shfl_xor_sync(FULL, msum, o);
        }
        if (lane == 0) {
            int se = msum - 1;
            g_score[b] = ns + end_t[labels[b * Tn + se]];
        }

        // ---- denominator: scaled linear-domain forward ----
        float Mc[Cn];
#pragma unroll
        for (int i = 0; i < Cn; i++) Mc[i] = act ? expf(trans[i * Cn + jj]) : 0.f;

        float p = act ? expf(start_t[jj] + em_sh[jj]) : 0.f;
        float logZ = 0.f;
        float emc = em_sh[Cn + jj];
        int   mkc = msk[1];

        for (int t = 1; t < Tn; t++) {
            float emn = em_sh[(t + 1) * Cn + jj];   // overrun lands in msk: harmless
            int   mkn = msk[t + 1];
            float Ev = __expf(emc);
            float q0 = 0.f, q1 = 0.f, q2 = 0.f, q3 = 0.f;
#pragma unroll
            for (int i = 0; i < Cn; i += 4) {
                q0 = fmaf(__shfl_sync(FULL, p, i + 0), Mc[i + 0], q0);
                q1 = fmaf(__shfl_sync(FULL, p, i + 1), Mc[i + 1], q1);
                q2 = fmaf(__shfl_sync(FULL, p, i + 2), Mc[i + 2], q2);
                q3 = fmaf(__shfl_sync(FULL, p, i + 3), Mc[i + 3], q3);
            }
            float r = ((q0 + q1) + (q2 + q3)) * Ev;
            p = (mkc > 0) ? r : p;
            if ((t & 15) == 0) {
                float s = p;
                for (int o = 16; o; o >>= 1) s += __shfl_xor_sync(FULL, s, o);
                p *= __fdividef(1.f, s);
                logZ += __logf(s);
            }
            emc = emn; mkc = mkn;
        }
        float fin = act ? p * __expf(end_t[jj]) : 0.f;
        for (int o = 16; o; o >>= 1) fin += __shfl_xor_sync(FULL, fin, o);
        if (lane == 0) g_norm[b] = logZ + __logf(fin);
        return;
    }

    // ======================= viterbi block =======================
    if (tid < 32) {
        // ---- pass 1: value recurrence only (warp 0); store a_t over em_sh[t]
        float Tc[Cn];
#pragma unroll
        for (int i = 0; i < Cn; i++) Tc[i] = act ? trans[i * Cn + jj] : 0.f;

        float a = act ? (start_t[jj] + em_sh[jj]) : neg_inf();
        if (act) em_sh[jj] = a;                      // a_0 over slot 0

        float emc = em_sh[Cn + jj];
        int   mkc = msk[1];

        for (int t = 1; t < Tn; t++) {
            float emn = em_sh[(t + 1) * Cn + jj];    // slot t+1 untouched yet
            int   mkn = msk[t + 1];

            float v[Cn];
#pragma unroll
            for (int i = 0; i < Cn; i++) v[i] = __shfl_sync(FULL, a, i) + Tc[i];

            float m0 = fmaxf(v[0],  v[1]);
            float m1 = fmaxf(v[2],  v[3]);
            float m2 = fmaxf(v[4],  v[5]);
            float m3 = fmaxf(v[6],  v[7]);
            float m4 = fmaxf(v[8],  v[9]);
            float m5 = fmaxf(v[10], v[11]);
            float m6 = fmaxf(v[12], v[13]);
            float m7 = fmaxf(v[14], v[15]);
            float m8 = fmaxf(v[16], v[17]);
            float m9 = fmaxf(v[18], v[19]);
            float n0 = fmaxf(m0, m1);
            float n1 = fmaxf(m2, m3);
            float n2 = fmaxf(m4, m5);
            float n3 = fmaxf(m6, m7);
            float n4 = fmaxf(m8, m9);
            float best = fmaxf(fmaxf(fmaxf(n0, n1), fmaxf(n2, n3)), n4);

            float na = best + emc;
            a = (mkc > 0) ? na : a;
            if (act) em_sh[t * Cn + jj] = a;         // post-mask a_t
            emc = emn; mkc = mkn;
        }

        // final argmax over states (first max on ties)
        float fv = act ? a + end_t[jj] : neg_inf();
        int fi = lane;
        for (int o = 16; o; o >>= 1) {
            float ov = __shfl_xor_sync(FULL, fv, o);
            int   oi = __shfl_xor_sync(FULL, fi, o);
            bool tk = (ov > fv) || (ov == fv && oi < fi);
            fv = tk ? ov : fv;
            fi = tk ? oi : fi;
        }
        if (lane == 0) misc[0] = fi;
    }
    __syncthreads();

    // ---- pass 2: backpointers in parallel from stored a trajectory ----
    if (tid < 120) {
        const int j = tid % Cn;          // my target state
        const int g = tid / Cn;          // 0..5
        float Tj[Cn];
#pragma unroll
        for (int i = 0; i < Cn; i++) Tj[i] = trans[i * Cn + j];

        for (int t = 1 + g; t < Tn; t += 6) {
            const float4* ap = (const float4*)(em_sh + (t - 1) * Cn);
            float4 A0 = ap[0], A1 = ap[1], A2 = ap[2], A3 = ap[3], A4 = ap[4];
            float v[Cn];
            v[0] = A0.x + Tj[0];  v[1] = A0.y + Tj[1];  v[2] = A0.z + Tj[2];  v[3] = A0.w + Tj[3];
            v[4] = A1.x + Tj[4];  v[5] = A1.y + Tj[5];  v[6] = A1.z + Tj[6];  v[7] = A1.w + Tj[7];
            v[8] = A2.x + Tj[8];  v[9] = A2.y + Tj[9];  v[10] = A2.z + Tj[10]; v[11] = A2.w + Tj[11];
            v[12] = A3.x + Tj[12]; v[13] = A3.y + Tj[13]; v[14] = A3.z + Tj[14]; v[15] = A3.w + Tj[15];
            v[16] = A4.x + Tj[16]; v[17] = A4.y + Tj[17]; v[18] = A4.z + Tj[18]; v[19] = A4.w + Tj[19];

            float m0 = fmaxf(v[0],  v[1]);
            float m1 = fmaxf(v[2],  v[3]);
            float m2 = fmaxf(v[4],  v[5]);
            float m3 = fmaxf(v[6],  v[7]);
            float m4 = fmaxf(v[8],  v[9]);
            float m5 = fmaxf(v[10], v[11]);
            float m6 = fmaxf(v[12], v[13]);
            float m7 = fmaxf(v[14], v[15]);
            float m8 = fmaxf(v[16], v[17]);
            float m9 = fmaxf(v[18], v[19]);
            float best = fmaxf(fmaxf(fmaxf(fmaxf(m0, m1), fmaxf(m2, m3)),
                                     fmaxf(fmaxf(m4, m5), fmaxf(m6, m7))),
                               fmaxf(m8, m9));
            unsigned eqm = 0;
#pragma unroll
            for (int i = 0; i < Cn; i++) eqm |= (v[i] == best) ? (1u << i) : 0u;
            hist8[(t - 1) * Cn + j] = (unsigned char)(__ffs(eqm) - 1);
        }
    }
    __syncthreads();

    // ---- serial backtrace into smem, then coalesced write-out ----
    float* pathf = (float*)msk;            // mask no longer needed
    if (tid == 0) {
        int tg = misc[0];
        pathf[Tn - 1] = (float)(tg + 1);
        for (int t = Tn - 2; t >= 0; t--) {
            tg = hist8[t * Cn + tg];
            pathf[t] = (float)(tg + 1);
        }
    }
    __syncthreads();
    float* od = dout + 1 + b * Tn;
#pragma unroll
    for (int i = 0; i < Tn / 128; i++) od[tid + 128 * i] = pathf[tid + 128 * i];
}

// ---------------------------------------------------------------------------
// Kernel 3: loss = mean(norm - score)   (one warp)
// ---------------------------------------------------------------------------
extern "C" __global__ void k_loss(float* __restrict__ dout) {
    int i = threadIdx.x;                          // 32 threads
    float v = g_norm[i] - g_score[i];
    v += g_norm[i + 32] - g_score[i + 32];
    for (int o = 16; o; o >>= 1) v += __shfl_xor_sync(FULL, v, o);
    if (i == 0) dout[0] = v / (float)Bn;
}

// ---------------------------------------------------------------------------
extern "C" void kernel_launch(void* const* d_in, const int* in_sizes, int n_in,
                              void* d_out, int out_size) {
    const float* hidden = (const float*)d_in[0];
    const int*   amask  = (const int*)d_in[1];
    const int*   labels = (const int*)d_in[2];
    const float* fc_w   = (const float*)d_in[3];
    const float* fc_b   = (const float*)d_in[4];
    const float* st     = (const float*)d_in[5];
    const float* en     = (const float*)d_in[6];
    const float* tr     = (const float*)d_in[7];
    float* dout = (float*)d_out;

    const int smem1 = (Cn * En + Cn) * 4;
    (void)cudaFuncSetAttribute((const void*)k_emissions,
                               cudaFuncAttributeMaxDynamicSharedMemorySize, smem1);
    (void)cudaFuncSetAttribute((const void*)k_crf,
                               cudaFuncAttributeMaxDynamicSharedMemorySize, SM2_SIZE);

    k_emissions<<<444, 256, smem1>>>(hidden, fc_w, fc_b);
    k_crf<<<2 * Bn, 128, SM2_SIZE>>>(amask, labels, st, en, tr, dout);
    k_loss<<<1, 32>>>(dout);
}

// round 7
// speedup vs baseline: 4.2888x; 1.0455x over previous
#include <cuda_runtime.h>
#include <math.h>

#define Bn 64
#define Tn 512
#define En 768
#define Cn 20
#define FULL 0xffffffffu

// scratch (no allocations allowed)
__device__ float g_em[Bn * Tn * Cn];   // emissions [B][T][C]
__device__ float g_norm[Bn];
__device__ float g_score[Bn];

__device__ __forceinline__ float neg_inf() { return __int_as_float(0xff800000); }

// ---------------------------------------------------------------------------
// Kernel 1: emissions = hidden @ fc_w^T + fc_b
// warp per ROW-PAIR; k-loop NOT unrolled (live set ~86 regs)
// launch_bounds(256,3): cap 84 regs -> 3 blocks/SM (24 warps) for latency cover
// ---------------------------------------------------------------------------
extern "C" __global__ void __launch_bounds__(256, 3)
k_emissions(const float* __restrict__ hidden,
            const float* __restrict__ fc_w,
            const float* __restrict__ fc_b) {
    extern __shared__ float sm[];          // Cn*En weights + Cn bias
    float* wsh = sm;
    float* bsh = sm + Cn * En;
    for (int i = threadIdx.x; i < Cn * En; i += blockDim.x) wsh[i] = fc_w[i];
    if (threadIdx.x < Cn) bsh[threadIdx.x] = fc_b[threadIdx.x];
    __syncthreads();

    const int lane  = threadIdx.x & 31;
    const int warp  = threadIdx.x >> 5;
    const int nwarp = (blockDim.x >> 5) * gridDim.x;
    const float4* w4 = (const float4*)wsh;
    const int npairs = Bn * Tn / 2;

    for (int pair = blockIdx.x * (blockDim.x >> 5) + warp; pair < npairs; pair += nwarp) {
        const float4* h0 = (const float4*)(hidden + (size_t)(2 * pair) * En);
        const float4* h1 = h0 + En / 4;
        float a0[Cn], a1[Cn];
#pragma unroll
        for (int c = 0; c < Cn; c++) { a0[c] = 0.f; a1[c] = 0.f; }

#pragma unroll 1
        for (int k = 0; k < En / 128; k++) {           // 6 chunks, NOT unrolled
            float4 x0 = h0[lane + 32 * k];
            float4 x1 = h1[lane + 32 * k];
#pragma unroll
            for (int c = 0; c < Cn; c++) {
                float4 w = w4[c * (En / 4) + lane + 32 * k];
                a0[c] = fmaf(x0.x, w.x, fmaf(x0.y, w.y, fmaf(x0.z, w.z, fmaf(x0.w, w.w, a0[c]))));
                a1[c] = fmaf(x1.x, w.x, fmaf(x1.y, w.y, fmaf(x1.z, w.z, fmaf(x1.w, w.w, a1[c]))));
            }
        }
#pragma unroll
        for (int c = 0; c < Cn; c++) {
#pragma unroll
            for (int o = 16; o; o >>= 1) {
                a0[c] += __shfl_xor_sync(FULL, a0[c], o);
                a1[c] += __shfl_xor_sync(FULL, a1[c], o);
            }
        }
        if (lane == 0) {
            float* out0 = g_em + (size_t)(2 * pair) * Cn;
            float4* o0 = (float4*)out0;
            float4* o1 = (float4*)(out0 + Cn);
            o0[0] = make_float4(a0[0]+bsh[0],   a0[1]+bsh[1],   a0[2]+bsh[2],   a0[3]+bsh[3]);
            o0[1] = make_float4(a0[4]+bsh[4],   a0[5]+bsh[5],   a0[6]+bsh[6],   a0[7]+bsh[7]);
            o0[2] = make_float4(a0[8]+bsh[8],   a0[9]+bsh[9],   a0[10]+bsh[10], a0[11]+bsh[11]);
            o0[3] = make_float4(a0[12]+bsh[12], a0[13]+bsh[13], a0[14]+bsh[14], a0[15]+bsh[15]);
            o0[4] = make_float4(a0[16]+bsh[16], a0[17]+bsh[17], a0[18]+bsh[18], a0[19]+bsh[19]);
            o1[0] = make_float4(a1[0]+bsh[0],   a1[1]+bsh[1],   a1[2]+bsh[2],   a1[3]+bsh[3]);
            o1[1] = make_float4(a1[4]+bsh[4],   a1[5]+bsh[5],   a1[6]+bsh[6],   a1[7]+bsh[7]);
            o1[2] = make_float4(a1[8]+bsh[8],   a1[9]+bsh[9],   a1[10]+bsh[10], a1[11]+bsh[11]);
            o1[3] = make_float4(a1[12]+bsh[12], a1[13]+bsh[13], a1[14]+bsh[14], a1[15]+bsh[15]);
            o1[4] = make_float4(a1[16]+bsh[16], a1[17]+bsh[17], a1[18]+bsh[18], a1[19]+bsh[19]);
        }
    }
}

// ---------------------------------------------------------------------------
// Kernel 2: blocks 0..63  -> numerator + scaled forward (warp 0)
//           blocks 64..127-> two-pass viterbi (pass1 warp0, pass2 all threads)
// ---------------------------------------------------------------------------
#define SM_EM    (Tn * Cn * 4)                 // 40960  emissions -> a trajectory
#define SM_MSK   (Tn * 4)                      // 2048   mask -> path buffer
#define SM_HIST  (Tn * Cn)                     // 10240  u8 backpointers
#define SM2_SIZE (SM_EM + SM_MSK + SM_HIST + 16)

extern "C" __global__ void __launch_bounds__(128)
k_crf(const int* __restrict__ amask,
      const int* __restrict__ labels,
      const float* __restrict__ start_t,
      const float* __restrict__ end_t,
      const float* __restrict__ trans,
      float* __restrict__ dout) {
    extern __shared__ char smraw[];
    float*         em_sh = (float*)smraw;
    int*           msk   = (int*)(smraw + SM_EM);
    unsigned char* hist8 = (unsigned char*)(smraw + SM_EM + SM_MSK);
    int*           misc  = (int*)(smraw + SM_EM + SM_MSK + SM_HIST);

    const int tid  = threadIdx.x;
    const bool isfwd = (blockIdx.x < Bn);
    const int b = isfwd ? blockIdx.x : blockIdx.x - Bn;

    // stage emissions + mask for this batch (all 4 warps)
    {
        const float4* src = (const float4*)(g_em + (size_t)b * Tn * Cn);
        float4* dst = (float4*)em_sh;
#pragma unroll 4
        for (int i = tid; i < Tn * Cn / 4; i += 128) dst[i] = src[i];
        for (int i = tid; i < Tn; i += 128) msk[i] = amask[b * Tn + i];
    }
    __syncthreads();

    const int lane = tid & 31;
    const bool act = lane < Cn;
    const int jj = act ? lane : 0;

    if (isfwd) {
        if (tid >= 32) return;
        // ---- numerator: gold path score ----
        float ns = 0.f; int msum = 0;
        for (int t = lane; t < Tn; t += 32) {
            int tg = labels[b * Tn + t];
            msum += msk[t];
            if (t == 0) {
                ns += start_t[tg] + em_sh[tg];
            } else if (msk[t]) {
                int tp = labels[b * Tn + t - 1];
                ns += trans[tp * Cn + tg] + em_sh[t * Cn + tg];
            }
        }
        for (int o = 16; o; o >>= 1) {
            ns   += __shfl_xor_sync(FULL, ns, o);
            msum += __shfl_xor_sync(FULL, msum, o);
        }
        if (lane == 0) {
            int se = msum - 1;
            g_score[b] = ns + end_t[labels[b * Tn + se]];
        }

        // ---- denominator: scaled linear-domain forward ----
        float Mc[Cn];
#pragma unroll
        for (int i = 0; i < Cn; i++) Mc[i] = act ? expf(trans[i * Cn + jj]) : 0.f;

        float p = act ? expf(start_t[jj] + em_sh[jj]) : 0.f;
        float logZ = 0.f;
        float emc = em_sh[Cn + jj];
        int   mkc = msk[1];

        for (int t = 1; t < Tn; t++) {
            float emn = em_sh[(t + 1) * Cn + jj];   // overrun lands in msk: harmless
            int   mkn = msk[t + 1];
            float Ev = __expf(emc);
            float q0 = 0.f, q1 = 0.f, q2 = 0.f, q3 = 0.f;
#pragma unroll
            for (int i = 0; i < Cn; i += 4) {
                q0 = fmaf(__shfl_sync(FULL, p, i + 0), Mc[i + 0], q0);
                q1 = fmaf(__shfl_sync(FULL, p, i + 1), Mc[i + 1], q1);
                q2 = fmaf(__shfl_sync(FULL, p, i + 2), Mc[i + 2], q2);
                q3 = fmaf(__shfl_sync(FULL, p, i + 3), Mc[i + 3], q3);
            }
            float r = ((q0 + q1) + (q2 + q3)) * Ev;
            p = (mkc > 0) ? r : p;
            if ((t & 15) == 0) {
                float s = p;
                for (int o = 16; o; o >>= 1) s += __shfl_xor_sync(FULL, s, o);
                p *= __fdividef(1.f, s);
                logZ += __logf(s);
            }
            emc = emn; mkc = mkn;
        }
        float fin = act ? p * __expf(end_t[jj]) : 0.f;
        for (int o = 16; o; o >>= 1) fin += __shfl_xor_sync(FULL, fin, o);
        if (lane == 0) g_norm[b] = logZ + __logf(fin);
        return;
    }

    // ======================= viterbi block =======================
    if (tid < 32) {
        // ---- pass 1: value recurrence only (warp 0); store a_t over em_sh[t]
        float Tc[Cn];
#pragma unroll
        for (int i = 0; i < Cn; i++) Tc[i] = act ? trans[i * Cn + jj] : 0.f;

        float a = act ? (start_t[jj] + em_sh[jj]) : neg_inf();
        if (act) em_sh[jj] = a;                      // a_0 over slot 0

        float emc = em_sh[Cn + jj];
        int   mkc = msk[1];

        for (int t = 1; t < Tn; t++) {
            float emn = em_sh[(t + 1) * Cn + jj];    // slot t+1 untouched yet
            int   mkn = msk[t + 1];

            float v[Cn];
#pragma unroll
            for (int i = 0; i < Cn; i++) v[i] = __shfl_sync(FULL, a, i) + Tc[i];

            float m0 = fmaxf(v[0],  v[1]);
            float m1 = fmaxf(v[2],  v[3]);
            float m2 = fmaxf(v[4],  v[5]);
            float m3 = fmaxf(v[6],  v[7]);
            float m4 = fmaxf(v[8],  v[9]);
            float m5 = fmaxf(v[10], v[11]);
            float m6 = fmaxf(v[12], v[13]);
            float m7 = fmaxf(v[14], v[15]);
            float m8 = fmaxf(v[16], v[17]);
            float m9 = fmaxf(v[18], v[19]);
            float n0 = fmaxf(m0, m1);
            float n1 = fmaxf(m2, m3);
            float n2 = fmaxf(m4, m5);
            float n3 = fmaxf(m6, m7);
            float n4 = fmaxf(m8, m9);
            float best = fmaxf(fmaxf(fmaxf(n0, n1), fmaxf(n2, n3)), n4);

            float na = best + emc;
            a = (mkc > 0) ? na : a;
            if (act) em_sh[t * Cn + jj] = a;         // post-mask a_t
            emc = emn; mkc = mkn;
        }

        // final argmax over states (first max on ties)
        float fv = act ? a + end_t[jj] : neg_inf();
        int fi = lane;
        for (int o = 16; o; o >>= 1) {
            float ov = __shfl_xor_sync(FULL, fv, o);
            int   oi = __shfl_xor_sync(FULL, fi, o);
            bool tk = (ov > fv) || (ov == fv && oi < fi);
            fv = tk ? ov : fv;
            fi = tk ? oi : fi;
        }
        if (lane == 0) misc[0] = fi;
    }
    __syncthreads();

    // ---- pass 2: backpointers in parallel from stored a trajectory ----
    if (tid < 120) {
        const int j = tid % Cn;          // my target state
        const int g = tid / Cn;          // 0..5
        float Tj[Cn];
#pragma unroll
        for (int i = 0; i < Cn; i++) Tj[i] = trans[i * Cn + j];

        for (int t = 1 + g; t < Tn; t += 6) {
            const float4* ap = (const float4*)(em_sh + (t - 1) * Cn);
            float4 A0 = ap[0], A1 = ap[1], A2 = ap[2], A3 = ap[3], A4 = ap[4];
            float v[Cn];
            v[0] = A0.x + Tj[0];  v[1] = A0.y + Tj[1];  v[2] = A0.z + Tj[2];  v[3] = A0.w + Tj[3];
            v[4] = A1.x + Tj[4];  v[5] = A1.y + Tj[5];  v[6] = A1.z + Tj[6];  v[7] = A1.w + Tj[7];
            v[8] = A2.x + Tj[8];  v[9] = A2.y + Tj[9];  v[10] = A2.z + Tj[10]; v[11] = A2.w + Tj[11];
            v[12] = A3.x + Tj[12]; v[13] = A3.y + Tj[13]; v[14] = A3.z + Tj[14]; v[15] = A3.w + Tj[15];
            v[16] = A4.x + Tj[16]; v[17] = A4.y + Tj[17]; v[18] = A4.z + Tj[18]; v[19] = A4.w + Tj[19];

            float m0 = fmaxf(v[0],  v[1]);
            float m1 = fmaxf(v[2],  v[3]);
            float m2 = fmaxf(v[4],  v[5]);
            float m3 = fmaxf(v[6],  v[7]);
            float m4 = fmaxf(v[8],  v[9]);
            float m5 = fmaxf(v[10], v[11]);
            float m6 = fmaxf(v[12], v[13]);
            float m7 = fmaxf(v[14], v[15]);
            float m8 = fmaxf(v[16], v[17]);
            float m9 = fmaxf(v[18], v[19]);
            float best = fmaxf(fmaxf(fmaxf(fmaxf(m0, m1), fmaxf(m2, m3)),
                                     fmaxf(fmaxf(m4, m5), fmaxf(m6, m7))),
                               fmaxf(m8, m9));
            unsigned eqm = 0;
#pragma unroll
            for (int i = 0; i < Cn; i++) eqm |= (v[i] == best) ? (1u << i) : 0u;
            hist8[(t - 1) * Cn + j] = (unsigned char)(__ffs(eqm) - 1);
        }
    }
    __syncthreads();

    // ---- serial backtrace into smem, then coalesced write-out ----
    float* pathf = (float*)msk;            // mask no longer needed
    if (tid == 0) {
        int tg = misc[0];
        pathf[Tn - 1] = (float)(tg + 1);
        for (int t = Tn - 2; t >= 0; t--) {
            tg = hist8[t * Cn + tg];
            pathf[t] = (float)(tg + 1);
        }
    }
    __syncthreads();
    float* od = dout + 1 + b * Tn;
#pragma unroll
    for (int i = 0; i < Tn / 128; i++) od[tid + 128 * i] = pathf[tid + 128 * i];
}

// ---------------------------------------------------------------------------
// Kernel 3: loss = mean(norm - score)   (one warp)
// ---------------------------------------------------------------------------
extern "C" __global__ void k_loss(float* __restrict__ dout) {
    int i = threadIdx.x;                          // 32 threads
    float v = g_norm[i] - g_score[i];
    v += g_norm[i + 32] - g_score[i + 32];
    for (int o = 16; o; o >>= 1) v += __shfl_xor_sync(FULL, v, o);
    if (i == 0) dout[0] = v / (float)Bn;
}

// ---------------------------------------------------------------------------
extern "C" void kernel_launch(void* const* d_in, const int* in_sizes, int n_in,
                              void* d_out, int out_size) {
    const float* hidden = (const float*)d_in[0];
    const int*   amask  = (const int*)d_in[1];
    const int*   labels = (const int*)d_in[2];
    const float* fc_w   = (const float*)d_in[3];
    const float* fc_b   = (const float*)d_in[4];
    const float* st     = (const float*)d_in[5];
    const float* en     = (const float*)d_in[6];
    const float* tr     = (const float*)d_in[7];
    float* dout = (float*)d_out;

    const int smem1 = (Cn * En + Cn) * 4;
    (void)cudaFuncSetAttribute((const void*)k_emissions,
                               cudaFuncAttributeMaxDynamicSharedMemorySize, smem1);
    (void)cudaFuncSetAttribute((const void*)k_crf,
                               cudaFuncAttributeMaxDynamicSharedMemorySize, SM2_SIZE);

    k_emissions<<<444, 256, smem1>>>(hidden, fc_w, fc_b);
    k_crf<<<2 * Bn, 128, SM2_SIZE>>>(amask, labels, st, en, tr, dout);
    k_loss<<<1, 32>>>(dout);
}

// round 8
// speedup vs baseline: 4.9172x; 1.1465x over previous
#include <cuda_runtime.h>
#include <math.h>

#define Bn 64
#define Tn 512
#define En 768
#define Cn 20
#define FULL 0xffffffffu

// scratch (no allocations allowed)
__device__ float g_em[Bn * Tn * Cn];   // emissions [B][T][C]
__device__ float g_norm[Bn];
__device__ float g_score[Bn];

__device__ __forceinline__ float neg_inf() { return __int_as_float(0xff800000); }

// ---------------------------------------------------------------------------
// Kernel 1: emissions = hidden @ fc_w^T + fc_b   (unchanged from R7 best)
// ---------------------------------------------------------------------------
extern "C" __global__ void __launch_bounds__(256, 3)
k_emissions(const float* __restrict__ hidden,
            const float* __restrict__ fc_w,
            const float* __restrict__ fc_b) {
    extern __shared__ float sm[];          // Cn*En weights + Cn bias
    float* wsh = sm;
    float* bsh = sm + Cn * En;
    for (int i = threadIdx.x; i < Cn * En; i += blockDim.x) wsh[i] = fc_w[i];
    if (threadIdx.x < Cn) bsh[threadIdx.x] = fc_b[threadIdx.x];
    __syncthreads();

    const int lane  = threadIdx.x & 31;
    const int warp  = threadIdx.x >> 5;
    const int nwarp = (blockDim.x >> 5) * gridDim.x;
    const float4* w4 = (const float4*)wsh;
    const int npairs = Bn * Tn / 2;

    for (int pair = blockIdx.x * (blockDim.x >> 5) + warp; pair < npairs; pair += nwarp) {
        const float4* h0 = (const float4*)(hidden + (size_t)(2 * pair) * En);
        const float4* h1 = h0 + En / 4;
        float a0[Cn], a1[Cn];
#pragma unroll
        for (int c = 0; c < Cn; c++) { a0[c] = 0.f; a1[c] = 0.f; }

#pragma unroll 1
        for (int k = 0; k < En / 128; k++) {           // 6 chunks, NOT unrolled
            float4 x0 = h0[lane + 32 * k];
            float4 x1 = h1[lane + 32 * k];
#pragma unroll
            for (int c = 0; c < Cn; c++) {
                float4 w = w4[c * (En / 4) + lane + 32 * k];
                a0[c] = fmaf(x0.x, w.x, fmaf(x0.y, w.y, fmaf(x0.z, w.z, fmaf(x0.w, w.w, a0[c]))));
                a1[c] = fmaf(x1.x, w.x, fmaf(x1.y, w.y, fmaf(x1.z, w.z, fmaf(x1.w, w.w, a1[c]))));
            }
        }
#pragma unroll
        for (int c = 0; c < Cn; c++) {
#pragma unroll
            for (int o = 16; o; o >>= 1) {
                a0[c] += __shfl_xor_sync(FULL, a0[c], o);
                a1[c] += __shfl_xor_sync(FULL, a1[c], o);
            }
        }
        if (lane == 0) {
            float* out0 = g_em + (size_t)(2 * pair) * Cn;
            float4* o0 = (float4*)out0;
            float4* o1 = (float4*)(out0 + Cn);
            o0[0] = make_float4(a0[0]+bsh[0],   a0[1]+bsh[1],   a0[2]+bsh[2],   a0[3]+bsh[3]);
            o0[1] = make_float4(a0[4]+bsh[4],   a0[5]+bsh[5],   a0[6]+bsh[6],   a0[7]+bsh[7]);
            o0[2] = make_float4(a0[8]+bsh[8],   a0[9]+bsh[9],   a0[10]+bsh[10], a0[11]+bsh[11]);
            o0[3] = make_float4(a0[12]+bsh[12], a0[13]+bsh[13], a0[14]+bsh[14], a0[15]+bsh[15]);
            o0[4] = make_float4(a0[16]+bsh[16], a0[17]+bsh[17], a0[18]+bsh[18], a0[19]+bsh[19]);
            o1[0] = make_float4(a1[0]+bsh[0],   a1[1]+bsh[1],   a1[2]+bsh[2],   a1[3]+bsh[3]);
            o1[1] = make_float4(a1[4]+bsh[4],   a1[5]+bsh[5],   a1[6]+bsh[6],   a1[7]+bsh[7]);
            o1[2] = make_float4(a1[8]+bsh[8],   a1[9]+bsh[9],   a1[10]+bsh[10], a1[11]+bsh[11]);
            o1[3] = make_float4(a1[12]+bsh[12], a1[13]+bsh[13], a1[14]+bsh[14], a1[15]+bsh[15]);
            o1[4] = make_float4(a1[16]+bsh[16], a1[17]+bsh[17], a1[18]+bsh[18], a1[19]+bsh[19]);
        }
    }
}

// ---------------------------------------------------------------------------
// Kernel 2: blocks 0..63  -> numerator + scaled forward (warp 0)
//           blocks 64..127-> two-pass viterbi (pass1 warp0, pass2 all threads)
// State exchange per step via smem slot overwrite + broadcast LDS (no SHFL
// storm: 20 MIO ops/step -> ~8)
// ---------------------------------------------------------------------------
#define SM_EM    (Tn * Cn * 4)                 // 40960  emissions -> state trajectory
#define SM_MSK   (Tn * 4)                      // 2048   mask -> path buffer
#define SM_HIST  (Tn * Cn)                     // 10240  u8 backpointers
#define SM2_SIZE (SM_EM + SM_MSK + SM_HIST + 16)

extern "C" __global__ void __launch_bounds__(128)
k_crf(const int* __restrict__ amask,
      const int* __restrict__ labels,
      const float* __restrict__ start_t,
      const float* __restrict__ end_t,
      const float* __restrict__ trans,
      float* __restrict__ dout) {
    extern __shared__ char smraw[];
    float*         em_sh = (float*)smraw;
    int*           msk   = (int*)(smraw + SM_EM);
    unsigned char* hist8 = (unsigned char*)(smraw + SM_EM + SM_MSK);
    int*           misc  = (int*)(smraw + SM_EM + SM_MSK + SM_HIST);

    const int tid  = threadIdx.x;
    const bool isfwd = (blockIdx.x < Bn);
    const int b = isfwd ? blockIdx.x : blockIdx.x - Bn;

    // stage emissions + mask for this batch (all 4 warps)
    {
        const float4* src = (const float4*)(g_em + (size_t)b * Tn * Cn);
        float4* dst = (float4*)em_sh;
#pragma unroll 4
        for (int i = tid; i < Tn * Cn / 4; i += 128) dst[i] = src[i];
        for (int i = tid; i < Tn; i += 128) msk[i] = amask[b * Tn + i];
    }
    __syncthreads();

    const int lane = tid & 31;
    const bool act = lane < Cn;
    const int jj = act ? lane : 0;

    if (isfwd) {
        if (tid >= 32) return;
        // ---- numerator: gold path score (reads em_sh before it is overwritten) ----
        float ns = 0.f; int msum = 0;
        for (int t = lane; t < Tn; t += 32) {
            int tg = labels[b * Tn + t];
            msum += msk[t];
            if (t == 0) {
                ns += start_t[tg] + em_sh[tg];
            } else if (msk[t]) {
                int tp = labels[b * Tn + t - 1];
                ns += trans[tp * Cn + tg] + em_sh[t * Cn + tg];
            }
        }
        for (int o = 16; o; o >>= 1) {
            ns   += __shfl_xor_sync(FULL, ns, o);
            msum += __shfl_xor_sync(FULL, msum, o);
        }
        if (lane == 0) {
            int se = msum - 1;
            g_score[b] = ns + end_t[labels[b * Tn + se]];
        }

        // ---- denominator: scaled linear-domain forward, smem state exchange ----
        float Mc[Cn];
#pragma unroll
        for (int i = 0; i < Cn; i++) Mc[i] = act ? expf(trans[i * Cn + jj]) : 0.f;

        float p = act ? expf(start_t[jj] + em_sh[jj]) : 0.f;
        if (act) em_sh[jj] = p;                      // p_0 over consumed slot 0
        __syncwarp();

        float logZ = 0.f;
        float emc = em_sh[Cn + jj];
        int   mkc = msk[1];

        for (int t = 1; t < Tn; t++) {
            float emn = em_sh[(t + 1) * Cn + jj];    // slot t+1 pristine; t=511 overruns into msk: unused
            int   mkn = msk[t + 1];
            float Ev = __expf(emc);
            const float4* pv = (const float4*)(em_sh + (t - 1) * Cn);  // p_{t-1}, broadcast
            float4 P0 = pv[0], P1 = pv[1], P2 = pv[2], P3 = pv[3], P4 = pv[4];
            float q0, q1, q2, q3;
            q0 = P0.x * Mc[0];             q1 = P0.y * Mc[1];
            q2 = P0.z * Mc[2];             q3 = P0.w * Mc[3];
            q0 = fmaf(P1.x, Mc[4],  q0);   q1 = fmaf(P1.y, Mc[5],  q1);
            q2 = fmaf(P1.z, Mc[6],  q2);   q3 = fmaf(P1.w, Mc[7],  q3);
            q0 = fmaf(P2.x, Mc[8],  q0);   q1 = fmaf(P2.y, Mc[9],  q1);
            q2 = fmaf(P2.z, Mc[10], q2);   q3 = fmaf(P2.w, Mc[11], q3);
            q0 = fmaf(P3.x, Mc[12], q0);   q1 = fmaf(P3.y, Mc[13], q1);
            q2 = fmaf(P3.z, Mc[14], q2);   q3 = fmaf(P3.w, Mc[15], q3);
            q0 = fmaf(P4.x, Mc[16], q0);   q1 = fmaf(P4.y, Mc[17], q1);
            q2 = fmaf(P4.z, Mc[18], q2);   q3 = fmaf(P4.w, Mc[19], q3);
            float r = ((q0 + q1) + (q2 + q3)) * Ev;
            p = act ? ((mkc > 0) ? r : p) : 0.f;
            if ((t & 15) == 0) {                     // renormalize every 16 steps
                float s = p;
                for (int o = 16; o; o >>= 1) s += __shfl_xor_sync(FULL, s, o);
                p *= __fdividef(1.f, s);
                logZ += __logf(s);
            }
            if (act) em_sh[t * Cn + jj] = p;         // publish p_t over consumed slot t
            __syncwarp();
            emc = emn; mkc = mkn;
        }
        float fin = act ? p * __expf(end_t[jj]) : 0.f;
        for (int o = 16; o; o >>= 1) fin += __shfl_xor_sync(FULL, fin, o);
        if (lane == 0) g_norm[b] = logZ + __logf(fin);
        return;
    }

    // ======================= viterbi block =======================
    if (tid < 32) {
        // ---- pass 1: value recurrence (warp 0); a_t published over em_sh[t]
        float Tc[Cn];
#pragma unroll
        for (int i = 0; i < Cn; i++) Tc[i] = act ? trans[i * Cn + jj] : 0.f;

        float a = act ? (start_t[jj] + em_sh[jj]) : 0.f;
        if (act) em_sh[jj] = a;                      // a_0 over slot 0
        __syncwarp();

        float emc = em_sh[Cn + jj];
        int   mkc = msk[1];

        for (int t = 1; t < Tn; t++) {
            float emn = em_sh[(t + 1) * Cn + jj];    // slot t+1 pristine
            int   mkn = msk[t + 1];

            const float4* av = (const float4*)(em_sh + (t - 1) * Cn);  // a_{t-1}, broadcast
            float4 A0 = av[0], A1 = av[1], A2 = av[2], A3 = av[3], A4 = av[4];
            float v0  = A0.x + Tc[0],  v1  = A0.y + Tc[1];
            float v2  = A0.z + Tc[2],  v3  = A0.w + Tc[3];
            float v4  = A1.x + Tc[4],  v5  = A1.y + Tc[5];
            float v6  = A1.z + Tc[6],  v7  = A1.w + Tc[7];
            float v8  = A2.x + Tc[8],  v9  = A2.y + Tc[9];
            float v10 = A2.z + Tc[10], v11 = A2.w + Tc[11];
            float v12 = A3.x + Tc[12], v13 = A3.y + Tc[13];
            float v14 = A3.z + Tc[14], v15 = A3.w + Tc[15];
            float v16 = A4.x + Tc[16], v17 = A4.y + Tc[17];
            float v18 = A4.z + Tc[18], v19 = A4.w + Tc[19];

            float m0 = fmaxf(v0,  v1);
            float m1 = fmaxf(v2,  v3);
            float m2 = fmaxf(v4,  v5);
            float m3 = fmaxf(v6,  v7);
            float m4 = fmaxf(v8,  v9);
            float m5 = fmaxf(v10, v11);
            float m6 = fmaxf(v12, v13);
            float m7 = fmaxf(v14, v15);
            float m8 = fmaxf(v16, v17);
            float m9 = fmaxf(v18, v19);
            float best = fmaxf(fmaxf(fmaxf(fmaxf(m0, m1), fmaxf(m2, m3)),
                                     fmaxf(fmaxf(m4, m5), fmaxf(m6, m7))),
                               fmaxf(m8, m9));

            float na = best + emc;
            a = (mkc > 0) ? na : a;
            if (act) em_sh[t * Cn + jj] = a;         // publish post-mask a_t
            __syncwarp();
            emc = emn; mkc = mkn;
        }

        // final argmax over states (first max on ties)
        float fv = act ? a + end_t[jj] : neg_inf();
        int fi = lane;
        for (int o = 16; o; o >>= 1) {
            float ov = __shfl_xor_sync(FULL, fv, o);
            int   oi = __shfl_xor_sync(FULL, fi, o);
            bool tk = (ov > fv) || (ov == fv && oi < fi);
            fv = tk ? ov : fv;
            fi = tk ? oi : fi;
        }
        if (lane == 0) misc[0] = fi;
    }
    __syncthreads();

    // ---- pass 2: backpointers in parallel from stored a trajectory ----
    if (tid < 120) {
        const int j = tid % Cn;          // my target state
        const int g = tid / Cn;          // 0..5
        float Tj[Cn];
#pragma unroll
        for (int i = 0; i < Cn; i++) Tj[i] = trans[i * Cn + j];

        for (int t = 1 + g; t < Tn; t += 6) {
            const float4* ap = (const float4*)(em_sh + (t - 1) * Cn);
            float4 A0 = ap[0], A1 = ap[1], A2 = ap[2], A3 = ap[3], A4 = ap[4];
            float v[Cn];
            v[0] = A0.x + Tj[0];  v[1] = A0.y + Tj[1];  v[2] = A0.z + Tj[2];  v[3] = A0.w + Tj[3];
            v[4] = A1.x + Tj[4];  v[5] = A1.y + Tj[5];  v[6] = A1.z + Tj[6];  v[7] = A1.w + Tj[7];
            v[8] = A2.x + Tj[8];  v[9] = A2.y + Tj[9];  v[10] = A2.z + Tj[10]; v[11] = A2.w + Tj[11];
            v[12] = A3.x + Tj[12]; v[13] = A3.y + Tj[13]; v[14] = A3.z + Tj[14]; v[15] = A3.w + Tj[15];
            v[16] = A4.x + Tj[16]; v[17] = A4.y + Tj[17]; v[18] = A4.z + Tj[18]; v[19] = A4.w + Tj[19];

            float m0 = fmaxf(v[0],  v[1]);
            float m1 = fmaxf(v[2],  v[3]);
            float m2 = fmaxf(v[4],  v[5]);
            float m3 = fmaxf(v[6],  v[7]);
            float m4 = fmaxf(v[8],  v[9]);
            float m5 = fmaxf(v[10], v[11]);
            float m6 = fmaxf(v[12], v[13]);
            float m7 = fmaxf(v[14], v[15]);
            float m8 = fmaxf(v[16], v[17]);
            float m9 = fmaxf(v[18], v[19]);
            float best = fmaxf(fmaxf(fmaxf(fmaxf(m0, m1), fmaxf(m2, m3)),
                                     fmaxf(fmaxf(m4, m5), fmaxf(m6, m7))),
                               fmaxf(m8, m9));
            unsigned eqm = 0;
#pragma unroll
            for (int i = 0; i < Cn; i++) eqm |= (v[i] == best) ? (1u << i) : 0u;
            hist8[(t - 1) * Cn + j] = (unsigned char)(__ffs(eqm) - 1);
        }
    }
    __syncthreads();

    // ---- serial backtrace into smem, then coalesced write-out ----
    float* pathf = (float*)msk;            // mask no longer needed
    if (tid == 0) {
        int tg = misc[0];
        pathf[Tn - 1] = (float)(tg + 1);
        for (int t = Tn - 2; t >= 0; t--) {
            tg = hist8[t * Cn + tg];
            pathf[t] = (float)(tg + 1);
        }
    }
    __syncthreads();
    float* od = dout + 1 + b * Tn;
#pragma unroll
    for (int i = 0; i < Tn / 128; i++) od[tid + 128 * i] = pathf[tid + 128 * i];
}

// ---------------------------------------------------------------------------
// Kernel 3: loss = mean(norm - score)   (one warp)
// ---------------------------------------------------------------------------
extern "C" __global__ void k_loss(float* __restrict__ dout) {
    int i = threadIdx.x;                          // 32 threads
    float v = g_norm[i] - g_score[i];
    v += g_norm[i + 32] - g_score[i + 32];
    for (int o = 16; o; o >>= 1) v += __shfl_xor_sync(FULL, v, o);
    if (i == 0) dout[0] = v / (float)Bn;
}

// ---------------------------------------------------------------------------
extern "C" void kernel_launch(void* const* d_in, const int* in_sizes, int n_in,
                              void* d_out, int out_size) {
    const float* hidden = (const float*)d_in[0];
    const int*   amask  = (const int*)d_in[1];
    const int*   labels = (const int*)d_in[2];
    const float* fc_w   = (const float*)d_in[3];
    const float* fc_b   = (const float*)d_in[4];
    const float* st     = (const float*)d_in[5];
    const float* en     = (const float*)d_in[6];
    const float* tr     = (const float*)d_in[7];
    float* dout = (float*)d_out;

    const int smem1 = (Cn * En + Cn) * 4;
    (void)cudaFuncSetAttribute((const void*)k_emissions,
                               cudaFuncAttributeMaxDynamicSharedMemorySize, smem1);
    (void)cudaFuncSetAttribute((const void*)k_crf,
                               cudaFuncAttributeMaxDynamicSharedMemorySize, SM2_SIZE);

    k_emissions<<<444, 256, smem1>>>(hidden, fc_w, fc_b);
    k_crf<<<2 * Bn, 128, SM2_SIZE>>>(amask, labels, st, en, tr, dout);
    k_loss<<<1, 32>>>(dout);
}

// round 9
// speedup vs baseline: 5.1207x; 1.0414x over previous
#include <cuda_runtime.h>
#include <math.h>

#define Bn 64
#define Tn 512
#define En 768
#define Cn 20
#define FULL 0xffffffffu

// scratch (no allocations allowed)
__device__ float g_em[Bn * Tn * Cn];   // emissions [B][T][C]
__device__ float g_norm[Bn];
__device__ float g_score[Bn];

__device__ __forceinline__ float neg_inf() { return __int_as_float(0xff800000); }

// ---------------------------------------------------------------------------
// Kernel 1: emissions = hidden @ fc_w^T + fc_b
// warp per ROW-QUAD (4-row register tile: weight LDS amortized over 4 rows)
// k-loop NOT unrolled; launch_bounds(256,2) -> cap 128 regs (live ~112)
// ---------------------------------------------------------------------------
extern "C" __global__ void __launch_bounds__(256, 2)
k_emissions(const float* __restrict__ hidden,
            const float* __restrict__ fc_w,
            const float* __restrict__ fc_b) {
    extern __shared__ float sm[];          // Cn*En weights + Cn bias
    float* wsh = sm;
    float* bsh = sm + Cn * En;
    for (int i = threadIdx.x; i < Cn * En; i += blockDim.x) wsh[i] = fc_w[i];
    if (threadIdx.x < Cn) bsh[threadIdx.x] = fc_b[threadIdx.x];
    __syncthreads();

    const int lane  = threadIdx.x & 31;
    const int warp  = threadIdx.x >> 5;
    const float4* w4 = (const float4*)wsh;

    const int quad = blockIdx.x * (blockDim.x >> 5) + warp;   // 1024*8 = 8192 quads
    const float4* h0 = (const float4*)(hidden + (size_t)(4 * quad) * En);
    const float4* h1 = h0 + En / 4;
    const float4* h2 = h1 + En / 4;
    const float4* h3 = h2 + En / 4;

    float a0[Cn], a1[Cn], a2[Cn], a3[Cn];
#pragma unroll
    for (int c = 0; c < Cn; c++) { a0[c] = 0.f; a1[c] = 0.f; a2[c] = 0.f; a3[c] = 0.f; }

#pragma unroll 1
    for (int k = 0; k < En / 128; k++) {           // 6 chunks, NOT unrolled
        float4 x0 = h0[lane + 32 * k];
        float4 x1 = h1[lane + 32 * k];
        float4 x2 = h2[lane + 32 * k];
        float4 x3 = h3[lane + 32 * k];
#pragma unroll
        for (int c = 0; c < Cn; c++) {
            float4 w = w4[c * (En / 4) + lane + 32 * k];
            a0[c] = fmaf(x0.x, w.x, fmaf(x0.y, w.y, fmaf(x0.z, w.z, fmaf(x0.w, w.w, a0[c]))));
            a1[c] = fmaf(x1.x, w.x, fmaf(x1.y, w.y, fmaf(x1.z, w.z, fmaf(x1.w, w.w, a1[c]))));
            a2[c] = fmaf(x2.x, w.x, fmaf(x2.y, w.y, fmaf(x2.z, w.z, fmaf(x2.w, w.w, a2[c]))));
            a3[c] = fmaf(x3.x, w.x, fmaf(x3.y, w.y, fmaf(x3.z, w.z, fmaf(x3.w, w.w, a3[c]))));
        }
    }
#pragma unroll
    for (int c = 0; c < Cn; c++) {
#pragma unroll
        for (int o = 16; o; o >>= 1) {
            a0[c] += __shfl_xor_sync(FULL, a0[c], o);
            a1[c] += __shfl_xor_sync(FULL, a1[c], o);
            a2[c] += __shfl_xor_sync(FULL, a2[c], o);
            a3[c] += __shfl_xor_sync(FULL, a3[c], o);
        }
    }
    // lanes 0..3 write rows 0..3 of the quad (spreads the store work)
    if (lane < 4) {
        const float* src = (lane == 0) ? a0 : (lane == 1) ? a1 : (lane == 2) ? a2 : a3;
        float4* o4 = (float4*)(g_em + (size_t)(4 * quad + lane) * Cn);
        o4[0] = make_float4(src[0]+bsh[0],   src[1]+bsh[1],   src[2]+bsh[2],   src[3]+bsh[3]);
        o4[1] = make_float4(src[4]+bsh[4],   src[5]+bsh[5],   src[6]+bsh[6],   src[7]+bsh[7]);
        o4[2] = make_float4(src[8]+bsh[8],   src[9]+bsh[9],   src[10]+bsh[10], src[11]+bsh[11]);
        o4[3] = make_float4(src[12]+bsh[12], src[13]+bsh[13], src[14]+bsh[14], src[15]+bsh[15]);
        o4[4] = make_float4(src[16]+bsh[16], src[17]+bsh[17], src[18]+bsh[18], src[19]+bsh[19]);
    }
}

// ---------------------------------------------------------------------------
// Kernel 2: blocks 0..63  -> numerator + scaled forward (warp 0)
//           blocks 64..127-> two-pass viterbi (pass1 warp0, pass2 all threads)
// State exchange per step via smem slot overwrite + broadcast LDS
// ---------------------------------------------------------------------------
#define SM_EM    (Tn * Cn * 4)                 // 40960  emissions -> state trajectory
#define SM_MSK   (Tn * 4)                      // 2048   mask -> path buffer
#define SM_HIST  (Tn * Cn)                     // 10240  u8 backpointers
#define SM2_SIZE (SM_EM + SM_MSK + SM_HIST + 16)

extern "C" __global__ void __launch_bounds__(128)
k_crf(const int* __restrict__ amask,
      const int* __restrict__ labels,
      const float* __restrict__ start_t,
      const float* __restrict__ end_t,
      const float* __restrict__ trans,
      float* __restrict__ dout) {
    extern __shared__ char smraw[];
    float*         em_sh = (float*)smraw;
    int*           msk   = (int*)(smraw + SM_EM);
    unsigned char* hist8 = (unsigned char*)(smraw + SM_EM + SM_MSK);
    int*           misc  = (int*)(smraw + SM_EM + SM_MSK + SM_HIST);

    const int tid  = threadIdx.x;
    const bool isfwd = (blockIdx.x < Bn);
    const int b = isfwd ? blockIdx.x : blockIdx.x - Bn;

    // stage emissions + mask for this batch (all 4 warps)
    {
        const float4* src = (const float4*)(g_em + (size_t)b * Tn * Cn);
        float4* dst = (float4*)em_sh;
#pragma unroll 4
        for (int i = tid; i < Tn * Cn / 4; i += 128) dst[i] = src[i];
        for (int i = tid; i < Tn; i += 128) msk[i] = amask[b * Tn + i];
    }
    __syncthreads();

    const int lane = tid & 31;
    const bool act = lane < Cn;
    const int jj = act ? lane : 0;

    if (isfwd) {
        if (tid >= 32) return;
        // ---- numerator: gold path score (reads em_sh before it is overwritten) ----
        float ns = 0.f; int msum = 0;
        for (int t = lane; t < Tn; t += 32) {
            int tg = labels[b * Tn + t];
            msum += msk[t];
            if (t == 0) {
                ns += start_t[tg] + em_sh[tg];
            } else if (msk[t]) {
                int tp = labels[b * Tn + t - 1];
                ns += trans[tp * Cn + tg] + em_sh[t * Cn + tg];
            }
        }
        for (int o = 16; o; o >>= 1) {
            ns   += __shfl_xor_sync(FULL, ns, o);
            msum += __shfl_xor_sync(FULL, msum, o);
        }
        if (lane == 0) {
            int se = msum - 1;
            g_score[b] = ns + end_t[labels[b * Tn + se]];
        }

        // ---- denominator: scaled linear-domain forward, smem state exchange ----
        float Mc[Cn];
#pragma unroll
        for (int i = 0; i < Cn; i++) Mc[i] = act ? expf(trans[i * Cn + jj]) : 0.f;

        float p = act ? expf(start_t[jj] + em_sh[jj]) : 0.f;
        if (act) em_sh[jj] = p;                      // p_0 over consumed slot 0
        __syncwarp();

        float logZ = 0.f;
        float emc = em_sh[Cn + jj];
        int   mkc = msk[1];

        for (int t = 1; t < Tn; t++) {
            float emn = em_sh[(t + 1) * Cn + jj];    // slot t+1 pristine; t=511 overruns into msk: unused
            int   mkn = msk[t + 1];
            float Ev = __expf(emc);
            const float4* pv = (const float4*)(em_sh + (t - 1) * Cn);  // p_{t-1}, broadcast
            float4 P0 = pv[0], P1 = pv[1], P2 = pv[2], P3 = pv[3], P4 = pv[4];
            float q0, q1, q2, q3;
            q0 = P0.x * Mc[0];             q1 = P0.y * Mc[1];
            q2 = P0.z * Mc[2];             q3 = P0.w * Mc[3];
            q0 = fmaf(P1.x, Mc[4],  q0);   q1 = fmaf(P1.y, Mc[5],  q1);
            q2 = fmaf(P1.z, Mc[6],  q2);   q3 = fmaf(P1.w, Mc[7],  q3);
            q0 = fmaf(P2.x, Mc[8],  q0);   q1 = fmaf(P2.y, Mc[9],  q1);
            q2 = fmaf(P2.z, Mc[10], q2);   q3 = fmaf(P2.w, Mc[11], q3);
            q0 = fmaf(P3.x, Mc[12], q0);   q1 = fmaf(P3.y, Mc[13], q1);
            q2 = fmaf(P3.z, Mc[14], q2);   q3 = fmaf(P3.w, Mc[15], q3);
            q0 = fmaf(P4.x, Mc[16], q0);   q1 = fmaf(P4.y, Mc[17], q1);
            q2 = fmaf(P4.z, Mc[18], q2);   q3 = fmaf(P4.w, Mc[19], q3);
            float r = ((q0 + q1) + (q2 + q3)) * Ev;
            p = act ? ((mkc > 0) ? r : p) : 0.f;
            if ((t & 15) == 0) {                     // renormalize every 16 steps
                float s = p;
                for (int o = 16; o; o >>= 1) s += __shfl_xor_sync(FULL, s, o);
                p *= __fdividef(1.f, s);
                logZ += __logf(s);
            }
            if (act) em_sh[t * Cn + jj] = p;         // publish p_t over consumed slot t
            __syncwarp();
            emc = emn; mkc = mkn;
        }
        float fin = act ? p * __expf(end_t[jj]) : 0.f;
        for (int o = 16; o; o >>= 1) fin += __shfl_xor_sync(FULL, fin, o);
        if (lane == 0) g_norm[b] = logZ + __logf(fin);
        return;
    }

    // ======================= viterbi block =======================
    if (tid < 32) {
        // ---- pass 1: value recurrence (warp 0); a_t published over em_sh[t]
        float Tc[Cn];
#pragma unroll
        for (int i = 0; i < Cn; i++) Tc[i] = act ? trans[i * Cn + jj] : 0.f;

        float a = act ? (start_t[jj] + em_sh[jj]) : 0.f;
        if (act) em_sh[jj] = a;                      // a_0 over slot 0
        __syncwarp();

        float emc = em_sh[Cn + jj];
        int   mkc = msk[1];

        for (int t = 1; t < Tn; t++) {
            float emn = em_sh[(t + 1) * Cn + jj];    // slot t+1 pristine
            int   mkn = msk[t + 1];

            const float4* av = (const float4*)(em_sh + (t - 1) * Cn);  // a_{t-1}, broadcast
            float4 A0 = av[0], A1 = av[1], A2 = av[2], A3 = av[3], A4 = av[4];
            float v0  = A0.x + Tc[0],  v1  = A0.y + Tc[1];
            float v2  = A0.z + Tc[2],  v3  = A0.w + Tc[3];
            float v4  = A1.x + Tc[4],  v5  = A1.y + Tc[5];
            float v6  = A1.z + Tc[6],  v7  = A1.w + Tc[7];
            float v8  = A2.x + Tc[8],  v9  = A2.y + Tc[9];
            float v10 = A2.z + Tc[10], v11 = A2.w + Tc[11];
            float v12 = A3.x + Tc[12], v13 = A3.y + Tc[13];
            float v14 = A3.z + Tc[14], v15 = A3.w + Tc[15];
            float v16 = A4.x + Tc[16], v17 = A4.y + Tc[17];
            float v18 = A4.z + Tc[18], v19 = A4.w + Tc[19];

            float m0 = fmaxf(v0,  v1);
            float m1 = fmaxf(v2,  v3);
            float m2 = fmaxf(v4,  v5);
            float m3 = fmaxf(v6,  v7);
            float m4 = fmaxf(v8,  v9);
            float m5 = fmaxf(v10, v11);
            float m6 = fmaxf(v12, v13);
            float m7 = fmaxf(v14, v15);
            float m8 = fmaxf(v16, v17);
            float m9 = fmaxf(v18, v19);
            float best = fmaxf(fmaxf(fmaxf(fmaxf(m0, m1), fmaxf(m2, m3)),
                                     fmaxf(fmaxf(m4, m5), fmaxf(m6, m7))),
                               fmaxf(m8, m9));

            float na = best + emc;
            a = (mkc > 0) ? na : a;
            if (act) em_sh[t * Cn + jj] = a;         // publish post-mask a_t
            __syncwarp();
            emc = emn; mkc = mkn;
        }

        // final argmax over states (first max on ties)
        float fv = act ? a + end_t[jj] : neg_inf();
        int fi = lane;
        for (int o = 16; o; o >>= 1) {
            float ov = __shfl_xor_sync(FULL, fv, o);
            int   oi = __shfl_xor_sync(FULL, fi, o);
            bool tk = (ov > fv) || (ov == fv && oi < fi);
            fv = tk ? ov : fv;
            fi = tk ? oi : fi;
        }
        if (lane == 0) misc[0] = fi;
    }
    __syncthreads();

    // ---- pass 2: backpointers in parallel from stored a trajectory ----
    if (tid < 120) {
        const int j = tid % Cn;          // my target state
        const int g = tid / Cn;          // 0..5
        float Tj[Cn];
#pragma unroll
        for (int i = 0; i < Cn; i++) Tj[i] = trans[i * Cn + j];

        for (int t = 1 + g; t < Tn; t += 6) {
            const float4* ap = (const float4*)(em_sh + (t - 1) * Cn);
            float4 A0 = ap[0], A1 = ap[1], A2 = ap[2], A3 = ap[3], A4 = ap[4];
            float v[Cn];
            v[0] = A0.x + Tj[0];  v[1] = A0.y + Tj[1];  v[2] = A0.z + Tj[2];  v[3] = A0.w + Tj[3];
            v[4] = A1.x + Tj[4];  v[5] = A1.y + Tj[5];  v[6] = A1.z + Tj[6];  v[7] = A1.w + Tj[7];
            v[8] = A2.x + Tj[8];  v[9] = A2.y + Tj[9];  v[10] = A2.z + Tj[10]; v[11] = A2.w + Tj[11];
            v[12] = A3.x + Tj[12]; v[13] = A3.y + Tj[13]; v[14] = A3.z + Tj[14]; v[15] = A3.w + Tj[15];
            v[16] = A4.x + Tj[16]; v[17] = A4.y + Tj[17]; v[18] = A4.z + Tj[18]; v[19] = A4.w + Tj[19];

            float m0 = fmaxf(v[0],  v[1]);
            float m1 = fmaxf(v[2],  v[3]);
            float m2 = fmaxf(v[4],  v[5]);
            float m3 = fmaxf(v[6],  v[7]);
            float m4 = fmaxf(v[8],  v[9]);
            float m5 = fmaxf(v[10], v[11]);
            float m6 = fmaxf(v[12], v[13]);
            float m7 = fmaxf(v[14], v[15]);
            float m8 = fmaxf(v[16], v[17]);
            float m9 = fmaxf(v[18], v[19]);
            float best = fmaxf(fmaxf(fmaxf(fmaxf(m0, m1), fmaxf(m2, m3)),
                                     fmaxf(fmaxf(m4, m5), fmaxf(m6, m7))),
                               fmaxf(m8, m9));
            unsigned eqm = 0;
#pragma unroll
            for (int i = 0; i < Cn; i++) eqm |= (v[i] == best) ? (1u << i) : 0u;
            hist8[(t - 1) * Cn + j] = (unsigned char)(__ffs(eqm) - 1);
        }
    }
    __syncthreads();

    // ---- serial backtrace into smem, then coalesced write-out ----
    float* pathf = (float*)msk;            // mask no longer needed
    if (tid == 0) {
        int tg = misc[0];
        pathf[Tn - 1] = (float)(tg + 1);
        for (int t = Tn - 2; t >= 0; t--) {
            tg = hist8[t * Cn + tg];
            pathf[t] = (float)(tg + 1);
        }
    }
    __syncthreads();
    float* od = dout + 1 + b * Tn;
#pragma unroll
    for (int i = 0; i < Tn / 128; i++) od[tid + 128 * i] = pathf[tid + 128 * i];
}

// ---------------------------------------------------------------------------
// Kernel 3: loss = mean(norm - score)   (one warp)
// ---------------------------------------------------------------------------
extern "C" __global__ void k_loss(float* __restrict__ dout) {
    int i = threadIdx.x;                          // 32 threads
    float v = g_norm[i] - g_score[i];
    v += g_norm[i + 32] - g_score[i + 32];
    for (int o = 16; o; o >>= 1) v += __shfl_xor_sync(FULL, v, o);
    if (i == 0) dout[0] = v / (float)Bn;
}

// ---------------------------------------------------------------------------
extern "C" void kernel_launch(void* const* d_in, const int* in_sizes, int n_in,
                              void* d_out, int out_size) {
    const float* hidden = (const float*)d_in[0];
    const int*   amask  = (const int*)d_in[1];
    const int*   labels = (const int*)d_in[2];
    const float* fc_w   = (const float*)d_in[3];
    const float* fc_b   = (const float*)d_in[4];
    const float* st     = (const float*)d_in[5];
    const float* en     = (const float*)d_in[6];
    const float* tr     = (const float*)d_in[7];
    float* dout = (float*)d_out;

    const int smem1 = (Cn * En + Cn) * 4;
    (void)cudaFuncSetAttribute((const void*)k_emissions,
                               cudaFuncAttributeMaxDynamicSharedMemorySize, smem1);
    (void)cudaFuncSetAttribute((const void*)k_crf,
                               cudaFuncAttributeMaxDynamicSharedMemorySize, SM2_SIZE);

    k_emissions<<<1024, 256, smem1>>>(hidden, fc_w, fc_b);   // 8192 quads
    k_crf<<<2 * Bn, 128, SM2_SIZE>>>(amask, labels, st, en, tr, dout);
    k_loss<<<1, 32>>>(dout);
}